// round 16
// baseline (speedup 1.0000x reference)
#include <cuda_runtime.h>
#include <cuda_fp16.h>
#include <math.h>
#include <math_constants.h>
#include <cstdint>

// Problem constants
#define BB  2
#define TT  2048
#define DDIM 1024
#define HH  16
#define DHH 64
#define MM  (BB*TT)

// ---------------------------------------------------------------------------
// Scratch (device globals)
// ---------------------------------------------------------------------------
__device__ float g_sin[TT * 32];
__device__ float g_cos[TT * 32];

__device__ __half g_a[(size_t)MM * DDIM];        // activations fp16 (x, later attn out)
__device__ __half g_w[(size_t)4 * DDIM * DDIM];  // weights transposed [N,K] fp16
__device__ __half g_qh[(size_t)MM * DDIM];       // q after rope
__device__ __half g_kh[(size_t)MM * DDIM];       // k after rope
__device__ __half g_vt[(size_t)MM * DDIM];       // v transposed [b,h,dh,T]

// ---------------------------------------------------------------------------
// Warp tensor helpers
// ---------------------------------------------------------------------------
__device__ __forceinline__ uint32_t smem_u32(const void* p) {
    uint32_t a;
    asm("{ .reg .u64 t; cvta.to.shared.u64 t, %1; cvt.u32.u64 %0, t; }"
        : "=r"(a) : "l"(p));
    return a;
}

__device__ __forceinline__ void ldm_x4(uint32_t* r, uint32_t addr) {
    asm volatile("ldmatrix.sync.aligned.m8n8.x4.shared.b16 {%0,%1,%2,%3}, [%4];"
                 : "=r"(r[0]), "=r"(r[1]), "=r"(r[2]), "=r"(r[3]) : "r"(addr));
}

__device__ __forceinline__ void mma_h(float* c, const uint32_t* a,
                                      const uint32_t* b) {
    asm volatile(
        "mma.sync.aligned.m16n8k16.row.col.f32.f16.f16.f32 "
        "{%0,%1,%2,%3}, {%4,%5,%6,%7}, {%8,%9}, {%0,%1,%2,%3};"
        : "+f"(c[0]), "+f"(c[1]), "+f"(c[2]), "+f"(c[3])
        : "r"(a[0]), "r"(a[1]), "r"(a[2]), "r"(a[3]), "r"(b[0]), "r"(b[1]));
}

__device__ __forceinline__ void cp16(uint32_t dst, const void* src) {
    asm volatile("cp.async.cg.shared.global [%0], [%1], 16;"
                 :: "r"(dst), "l"(src));
}
#define CP_COMMIT() asm volatile("cp.async.commit_group;" ::: "memory")
#define CP_WAIT0()  asm volatile("cp.async.wait_group 0;" ::: "memory")
#define CP_WAIT1()  asm volatile("cp.async.wait_group 1;" ::: "memory")

// pack 2 floats to f16x2: low half = first arg
__device__ __forceinline__ uint32_t cvt_h2(float lo, float hi) {
    uint32_t r;
    asm("cvt.rn.f16x2.f32 %0, %1, %2;" : "=r"(r) : "f"(hi), "f"(lo));
    return r;
}

// ---------------------------------------------------------------------------
// RoPE sin/cos table
// ---------------------------------------------------------------------------
__global__ void sincos_kernel() {
    int idx = blockIdx.x * blockDim.x + threadIdx.x;
    if (idx >= TT * 32) return;
    int t  = idx >> 5;
    int jj = idx & 31;
    double ang = (double)t * pow(10000.0, -2.0 * (double)jj / 64.0);
    g_sin[idx] = (float)sin(ang);
    g_cos[idx] = (float)cos(ang);
}

// ---------------------------------------------------------------------------
// fp32 -> fp16 convert (vectorized)
// ---------------------------------------------------------------------------
__global__ void conv_kernel(const float* __restrict__ src,
                            __half* __restrict__ dst, int n4) {
    int i = blockIdx.x * blockDim.x + threadIdx.x;
    if (i >= n4) return;
    float4 v = ((const float4*)src)[i];
    uint2 o;
    o.x = cvt_h2(v.x, v.y);
    o.y = cvt_h2(v.z, v.w);
    ((uint2*)dst)[i] = o;
}

// fp32 W[K,N] -> fp16 transposed [N,K]; all 4 weights in one launch (z)
__global__ void convT_kernel(const float* __restrict__ w0,
                             const float* __restrict__ w1,
                             const float* __restrict__ w2,
                             const float* __restrict__ w3) {
    __shared__ float tile[32][33];
    int z = blockIdx.z;
    const float* w = (z == 0) ? w0 : (z == 1) ? w1 : (z == 2) ? w2 : w3;
    __half* o = g_w + (size_t)z * DDIM * DDIM;
    int bx = blockIdx.x * 32;
    int by = blockIdx.y * 32;
    int tx = threadIdx.x, ty = threadIdx.y;
#pragma unroll
    for (int i = 0; i < 32; i += 8)
        tile[ty + i][tx] = w[(size_t)(by + ty + i) * DDIM + bx + tx];
    __syncthreads();
#pragma unroll
    for (int i = 0; i < 32; i += 8)
        o[(size_t)(bx + ty + i) * DDIM + by + tx] = __float2half(tile[tx][ty + i]);
}

// ---------------------------------------------------------------------------
// Shared GEMM mainloop: 8 warps, warp tile 64x32, kTile=64, 3-stage cp.async
// pipeline with ONE __syncthreads per iteration.
// ---------------------------------------------------------------------------
#define GT_ROW 144       // bytes per smem row (72 halves)
#define GT_ARR 18432     // bytes per tile array (128*144)
#define GT_BUF 36864     // bytes per stage (A + B)
#define GEMM_SMEM (3 * GT_BUF)   // 110592; 2 CTA/SM = 216KB <= 228KB

#define G_LOAD(kt, buf) do {                                                  \
        int k0_ = (kt) * 64;                                                  \
        _Pragma("unroll")                                                     \
        for (int q_ = 0; q_ < 4; q_++) {                                      \
            int row_ = q_ * 32 + ld_row;                                      \
            size_t ga_ = (size_t)(bm + row_) * DDIM + k0_ + ld_cg;            \
            size_t gb_ = (size_t)(bn + row_) * DDIM + k0_ + ld_cg;            \
            uint32_t so_ = sb + (buf) * GT_BUF + row_ * GT_ROW + ld_cg * 2;   \
            cp16(so_, A + ga_);                                               \
            cp16(so_ + GT_ARR, Bw + gb_);                                     \
        } } while (0)

// 3-stage pipeline. Invariant: at iter kt the single barrier (all warps done
// computing kt-1) protects buffer (kt+2)%3 == (kt-1)%3 before it is reloaded.
#define G_MAINLOOP()                                                          \
    G_LOAD(0, 0);                                                             \
    CP_COMMIT();                                                              \
    G_LOAD(1, 1);                                                             \
    CP_COMMIT();                                                              \
    for (int kt = 0; kt < 16; kt++) {                                         \
        if (kt < 14) { CP_WAIT1(); } else { CP_WAIT0(); }                     \
        __syncthreads();                                                      \
        if (kt + 2 < 16) { G_LOAD(kt + 2, (kt + 2) % 3); CP_COMMIT(); }       \
        const uint32_t bufb = sb + (kt % 3) * GT_BUF;                         \
        _Pragma("unroll")                                                     \
        for (int ko = 0; ko < 64; ko += 16) {                                 \
            uint32_t bfr[4][2];                                               \
            _Pragma("unroll")                                                 \
            for (int p = 0; p < 2; p++) {                                     \
                uint32_t t4[4];                                               \
                uint32_t boff = (wn + p * 16 + b_n) * GT_ROW + (ko + b_kof) * 2; \
                ldm_x4(t4, bufb + GT_ARR + boff);                             \
                bfr[p * 2][0] = t4[0]; bfr[p * 2][1] = t4[1];                 \
                bfr[p * 2 + 1][0] = t4[2]; bfr[p * 2 + 1][1] = t4[3];         \
            }                                                                 \
            _Pragma("unroll")                                                 \
            for (int mf = 0; mf < 4; mf++) {                                  \
                uint32_t ar[4];                                               \
                uint32_t aoff = (wm + mf * 16 + a_row) * GT_ROW + (ko + a_kof) * 2; \
                ldm_x4(ar, bufb + aoff);                                      \
                _Pragma("unroll")                                             \
                for (int nf = 0; nf < 4; nf++)                                \
                    mma_h(acc[mf][nf], ar, bfr[nf]);                          \
            }                                                                 \
        }                                                                     \
    }

#define G_PROLOG_BODY()                                                       \
    extern __shared__ char gsm[];                                             \
    const uint32_t sb = smem_u32(gsm);                                        \
    const int tid = threadIdx.x;                                              \
    const int lane = tid & 31;                                                \
    const int wid = tid >> 5;                                                 \
    const int wm = (wid & 1) * 64;                                            \
    const int wn = (wid >> 1) * 32;                                           \
    const int bn = blockIdx.x * 128;                                          \
    const int bm = blockIdx.y * 128;                                          \
    float acc[4][4][4];                                                       \
    _Pragma("unroll")                                                         \
    for (int i = 0; i < 4; i++)                                               \
        _Pragma("unroll")                                                     \
        for (int j = 0; j < 4; j++)                                           \
            _Pragma("unroll")                                                 \
            for (int r = 0; r < 4; r++) acc[i][j][r] = 0.f;                   \
    const int a_row = lane & 15;                                              \
    const int a_kof = (lane >> 4) << 3;                                       \
    const int b_n   = (lane & 7) + ((lane >> 4) << 3);                        \
    const int b_kof = ((lane >> 3) & 1) << 3;                                 \
    const int ld_row = tid >> 3;                                              \
    const int ld_cg  = (tid & 7) * 8;

// Store acc + bias into fp32 staging smem [128][129].
// Leading barrier: mainloop no longer ends with one (smem still being read).
#define G_STAGE_SMEM()                                                        \
    __syncthreads();                                                          \
    float* Ssm = (float*)gsm;                                                 \
    {                                                                         \
        const int qr = lane >> 2;                                             \
        const int qc = (lane & 3) * 2;                                        \
        _Pragma("unroll")                                                     \
        for (int mf = 0; mf < 4; mf++) {                                      \
            _Pragma("unroll")                                                 \
            for (int nf = 0; nf < 4; nf++) {                                  \
                int row = wm + mf * 16 + qr;                                  \
                int col = wn + nf * 8 + qc;                                   \
                float b0 = bias[bn + col], b1 = bias[bn + col + 1];           \
                Ssm[row * 129 + col]     = acc[mf][nf][0] + b0;               \
                Ssm[row * 129 + col + 1] = acc[mf][nf][1] + b1;               \
                Ssm[(row + 8) * 129 + col]     = acc[mf][nf][2] + b0;         \
                Ssm[(row + 8) * 129 + col + 1] = acc[mf][nf][3] + b1;         \
            }                                                                 \
        }                                                                     \
    }                                                                         \
    __syncthreads();

// ---------------------------------------------------------------------------
// Fused QKV projection: grid (8, 32, 3); z selects weight slab + epilogue.
// ---------------------------------------------------------------------------
__global__ void __launch_bounds__(256, 2) mma_gemm_qkv(
    const __half* __restrict__ A,
    const float* __restrict__ bqv, const float* __restrict__ bkv,
    const float* __restrict__ bvv)
{
    const int z = blockIdx.z;
    const __half* Bw = g_w + (size_t)z * DDIM * DDIM;
    const float* bias = (z == 0) ? bqv : (z == 1) ? bkv : bvv;

    G_PROLOG_BODY();
    G_MAINLOOP();
    G_STAGE_SMEM();

    if (z < 2) {
        // ---- rope epilogue -> g_qh / g_kh ----
        __half* O = (z == 0) ? g_qh : g_kh;
        for (int p = tid; p < 8192; p += 256) {
            int j  = p & 31;
            int hh = (p >> 5) & 1;
            int m  = p >> 6;
            int gm = bm + m;
            int t  = gm & (TT - 1);
            int cb = hh * 64;
            float a  = Ssm[m * 129 + cb + j];
            float bv = Ssm[m * 129 + cb + j + 32];
            int jj = j >> 1;
            float c1 = g_cos[t * 32 + jj],      s1 = g_sin[t * 32 + jj];
            float c2 = g_cos[t * 32 + jj + 16], s2 = g_sin[t * 32 + jj + 16];
            float o0 = a * c1 - bv * s1;
            float o1 = bv * c2 + a * s2;
            size_t off = (size_t)gm * DDIM + bn + cb + j;
            O[off]      = __float2half(o0);
            O[off + 32] = __float2half(o1);
        }
    } else {
        // ---- vt epilogue: transpose -> g_vt[b,h,dh,T] ----
        const int bq_ = bm >> 11;
        const int tm  = bm & (TT - 1);
#pragma unroll
        for (int ci = 0; ci < 16; ci++) {
            int c = wid + ci * 8;
            int gcol = bn + c;
            int hh = gcol >> 6, d = gcol & 63;
            size_t obase = ((size_t)(bq_ * HH + hh) * DHH + d) * TT + tm;
#pragma unroll
            for (int rj = 0; rj < 4; rj++) {
                int row = lane + rj * 32;
                g_vt[obase + row] = __float2half(Ssm[row * 129 + c]);
            }
        }
    }
}

// ---------------------------------------------------------------------------
// Plain GEMM: fp32 output + bias (out-projection). Register epilogue only.
// ---------------------------------------------------------------------------
__global__ void __launch_bounds__(256, 2) mma_gemm(
    const __half* __restrict__ A, const __half* __restrict__ Bw,
    const float* __restrict__ bias, float* __restrict__ C)
{
    G_PROLOG_BODY();
    G_MAINLOOP();

    const int qr = lane >> 2;
    const int qc = (lane & 3) * 2;
#pragma unroll
    for (int mf = 0; mf < 4; mf++) {
#pragma unroll
        for (int nf = 0; nf < 4; nf++) {
            int col = bn + wn + nf * 8 + qc;
            float b0 = bias[col], b1 = bias[col + 1];
            int r0 = bm + wm + mf * 16 + qr;
            float2 v0 = {acc[mf][nf][0] + b0, acc[mf][nf][1] + b1};
            float2 v1 = {acc[mf][nf][2] + b0, acc[mf][nf][3] + b1};
            *(float2*)&C[(size_t)r0 * DDIM + col] = v0;
            *(float2*)&C[(size_t)(r0 + 8) * DDIM + col] = v1;
        }
    }
}

// ---------------------------------------------------------------------------
// Flash attention, fp16 single-pass, 3-stage cp.async K/V pipeline,
// ONE barrier per k-iteration.
// ---------------------------------------------------------------------------
#define AT_ROW 144
#define AT_ARR 9216
#define AT_BUF 18432
#define ATTN_SMEM (3 * AT_BUF)   // 55296

__global__ void __launch_bounds__(256) attn_mma_kernel() {
    extern __shared__ char gsm[];
    const uint32_t sb = smem_u32(gsm);

    const int q0 = (gridDim.x - 1 - blockIdx.x) * 128;  // heavy blocks first
    const int h  = blockIdx.y;
    const int b  = blockIdx.z;
    const int tid = threadIdx.x;
    const int lane = tid & 31;
    const int wid = tid >> 5;
    const int wm = wid * 16;

    const size_t base_qk = (size_t)b * TT * DDIM + (size_t)h * DHH;
    const size_t base_vt = ((size_t)(b * HH + h)) * DHH * TT;

    const int a_row = lane & 15;
    const int a_kof = (lane >> 4) << 3;
    const int b_n   = (lane & 7) + ((lane >> 4) << 3);
    const int b_kof = ((lane >> 3) & 1) << 3;

    // ---- stage Q tile (buffer-0 region), load Q frags to registers ----
    for (int i = tid; i < 128 * 8; i += 256) {
        int r = i >> 3, c = (i & 7) * 8;
        size_t g = base_qk + (size_t)(q0 + r) * DDIM + c;
        *(uint4*)(gsm + r * AT_ROW + c * 2) = *(const uint4*)&g_qh[g];
    }
    __syncthreads();

    uint32_t qf[4][4];
#pragma unroll
    for (int ko = 0; ko < 4; ko++) {
        uint32_t aoff = (wm + a_row) * AT_ROW + (ko * 16 + a_kof) * 2;
        ldm_x4(qf[ko], sb + aoff);
    }
    __syncthreads();  // Q consumed; buffers free

    float m0 = -CUDART_INF_F, m1 = -CUDART_INF_F;
    float l0 = 0.f, l1 = 0.f;
    float o[8][4];
#pragma unroll
    for (int nf = 0; nf < 8; nf++)
#pragma unroll
        for (int r = 0; r < 4; r++) o[nf][r] = 0.f;

    const int nkt = q0 / 64 + 2;   // always >= 2
    const float scale = 0.125f;

#define A_LOAD(kt, buf) do {                                                  \
        int k0_ = (kt) * 64;                                                  \
        _Pragma("unroll")                                                     \
        for (int i = tid; i < 512; i += 256) {                                \
            int r_ = i >> 3, c_ = (i & 7) * 8;                                \
            uint32_t so_ = sb + (buf) * AT_BUF + r_ * AT_ROW + c_ * 2;        \
            size_t gk_ = base_qk + (size_t)(k0_ + r_) * DDIM + c_;            \
            size_t gv_ = base_vt + (size_t)r_ * TT + k0_ + c_;                \
            cp16(so_, g_kh + gk_);                                            \
            cp16(so_ + AT_ARR, g_vt + gv_);                                   \
        } } while (0)

    A_LOAD(0, 0);
    CP_COMMIT();
    A_LOAD(1, 1);
    CP_COMMIT();

    for (int kt = 0; kt < nkt; kt++) {
        const int k0 = kt * 64;
        if (kt < nkt - 2) { CP_WAIT1(); } else { CP_WAIT0(); }
        __syncthreads();
        if (kt + 2 < nkt) { A_LOAD(kt + 2, (kt + 2) % 3); CP_COMMIT(); }

        const uint32_t bufb = sb + (kt % 3) * AT_BUF;

        if (k0 <= q0 + wm + 15) {
            float s[8][4];
#pragma unroll
            for (int nf = 0; nf < 8; nf++)
#pragma unroll
                for (int r = 0; r < 4; r++) s[nf][r] = 0.f;

#pragma unroll
            for (int ko = 0; ko < 4; ko++) {
#pragma unroll
                for (int p = 0; p < 4; p++) {
                    uint32_t th[4];
                    uint32_t boff = (p * 16 + b_n) * AT_ROW + (ko * 16 + b_kof) * 2;
                    ldm_x4(th, bufb + boff);
                    mma_h(s[2 * p],     qf[ko], th);
                    mma_h(s[2 * p + 1], qf[ko], th + 2);
                }
            }

            const int qa = q0 + wm + (lane >> 2);
            const int qb = qa + 8;
            const bool need_mask = (k0 + 63 > q0 + wm);
#pragma unroll
            for (int nf = 0; nf < 8; nf++) {
                int cg = k0 + nf * 8 + (lane & 3) * 2;
                s[nf][0] *= scale; s[nf][1] *= scale;
                s[nf][2] *= scale; s[nf][3] *= scale;
                if (need_mask) {
                    if (cg > qa)     s[nf][0] = -10000.f;
                    if (cg + 1 > qa) s[nf][1] = -10000.f;
                    if (cg > qb)     s[nf][2] = -10000.f;
                    if (cg + 1 > qb) s[nf][3] = -10000.f;
                }
            }

            float rma = -CUDART_INF_F, rmb = -CUDART_INF_F;
#pragma unroll
            for (int nf = 0; nf < 8; nf++) {
                rma = fmaxf(rma, fmaxf(s[nf][0], s[nf][1]));
                rmb = fmaxf(rmb, fmaxf(s[nf][2], s[nf][3]));
            }
            rma = fmaxf(rma, __shfl_xor_sync(0xffffffffu, rma, 1));
            rma = fmaxf(rma, __shfl_xor_sync(0xffffffffu, rma, 2));
            rmb = fmaxf(rmb, __shfl_xor_sync(0xffffffffu, rmb, 1));
            rmb = fmaxf(rmb, __shfl_xor_sync(0xffffffffu, rmb, 2));
            float nma = fmaxf(m0, rma), nmb = fmaxf(m1, rmb);
            float alpha_a = __expf(m0 - nma), alpha_b = __expf(m1 - nmb);
            m0 = nma; m1 = nmb;

            float rsa = 0.f, rsb = 0.f;
#pragma unroll
            for (int nf = 0; nf < 8; nf++) {
                s[nf][0] = __expf(s[nf][0] - nma);
                s[nf][1] = __expf(s[nf][1] - nma);
                s[nf][2] = __expf(s[nf][2] - nmb);
                s[nf][3] = __expf(s[nf][3] - nmb);
                rsa += s[nf][0] + s[nf][1];
                rsb += s[nf][2] + s[nf][3];
            }
            rsa += __shfl_xor_sync(0xffffffffu, rsa, 1);
            rsa += __shfl_xor_sync(0xffffffffu, rsa, 2);
            rsb += __shfl_xor_sync(0xffffffffu, rsb, 1);
            rsb += __shfl_xor_sync(0xffffffffu, rsb, 2);
            l0 = l0 * alpha_a + rsa;
            l1 = l1 * alpha_b + rsb;

#pragma unroll
            for (int nf = 0; nf < 8; nf++) {
                o[nf][0] *= alpha_a; o[nf][1] *= alpha_a;
                o[nf][2] *= alpha_b; o[nf][3] *= alpha_b;
            }

            uint32_t ph[4][4];
#pragma unroll
            for (int kb = 0; kb < 4; kb++) {
                float* f0 = s[2 * kb];
                float* f1 = s[2 * kb + 1];
                ph[kb][0] = cvt_h2(f0[0], f0[1]);
                ph[kb][1] = cvt_h2(f0[2], f0[3]);
                ph[kb][2] = cvt_h2(f1[0], f1[1]);
                ph[kb][3] = cvt_h2(f1[2], f1[3]);
            }

#pragma unroll
            for (int kb = 0; kb < 4; kb++) {
#pragma unroll
                for (int p = 0; p < 4; p++) {
                    uint32_t th[4];
                    uint32_t boff = (p * 16 + b_n) * AT_ROW + (kb * 16 + b_kof) * 2;
                    ldm_x4(th, bufb + AT_ARR + boff);
                    mma_h(o[2 * p],     ph[kb], th);
                    mma_h(o[2 * p + 1], ph[kb], th + 2);
                }
            }
        }
    }
#undef A_LOAD

    // ---- epilogue: normalize + write fp16 into g_a (gmem only; no smem) ----
    float inv_a = 1.0f / l0, inv_b = 1.0f / l1;
    int ra = q0 + wm + (lane >> 2);
    int cq = (lane & 3) * 2;
#pragma unroll
    for (int nf = 0; nf < 8; nf++) {
        int col = h * DHH + nf * 8 + cq;
        float v0 = o[nf][0] * inv_a, v1 = o[nf][1] * inv_a;
        float v2 = o[nf][2] * inv_b, v3 = o[nf][3] * inv_b;
        size_t o0 = ((size_t)b * TT + ra) * DDIM + col;
        size_t o1 = ((size_t)b * TT + ra + 8) * DDIM + col;
        *(uint32_t*)&g_a[o0] = cvt_h2(v0, v1);
        *(uint32_t*)&g_a[o1] = cvt_h2(v2, v3);
    }
}

// ---------------------------------------------------------------------------
// Launch
// ---------------------------------------------------------------------------
extern "C" void kernel_launch(void* const* d_in, const int* in_sizes, int n_in,
                              void* d_out, int out_size)
{
    const float* x  = (const float*)d_in[0];
    const float* wq = (const float*)d_in[2];
    const float* bq = (const float*)d_in[3];
    const float* wk = (const float*)d_in[4];
    const float* bk = (const float*)d_in[5];
    const float* wv = (const float*)d_in[6];
    const float* bv = (const float*)d_in[7];
    const float* wo = (const float*)d_in[8];
    const float* bo = (const float*)d_in[9];
    float* out = (float*)d_out;

    __half *ap, *wp;
    cudaGetSymbolAddress((void**)&ap, g_a);
    cudaGetSymbolAddress((void**)&wp, g_w);

    const size_t WSZ = (size_t)DDIM * DDIM;

    sincos_kernel<<<(TT * 32 + 255) / 256, 256>>>();

    const int n4 = MM * DDIM / 4;
    conv_kernel<<<(n4 + 255) / 256, 256>>>(x, ap, n4);
    convT_kernel<<<dim3(32, 32, 4), dim3(32, 8)>>>(wq, wk, wv, wo);

    cudaFuncSetAttribute(mma_gemm_qkv,
                         cudaFuncAttributeMaxDynamicSharedMemorySize, GEMM_SMEM);
    cudaFuncSetAttribute(mma_gemm,
                         cudaFuncAttributeMaxDynamicSharedMemorySize, GEMM_SMEM);

    // Fused Q/K/V projections: one launch, 768 blocks
    mma_gemm_qkv<<<dim3(DDIM / 128, MM / 128, 3), 256, GEMM_SMEM>>>(
        ap, bq, bk, bv);

    // flash attention (overwrites g_a with fp16 attention output)
    cudaFuncSetAttribute(attn_mma_kernel,
                         cudaFuncAttributeMaxDynamicSharedMemorySize, ATTN_SMEM);
    attn_mma_kernel<<<dim3(TT / 128, HH, BB), 256, ATTN_SMEM>>>();

    // out-projection -> fp32 output
    mma_gemm<<<dim3(DDIM / 128, MM / 128), 256, GEMM_SMEM>>>(
        ap, wp + 3 * WSZ, bo, out);
}